// round 16
// baseline (speedup 1.0000x reference)
#include <cuda_runtime.h>

// Problem constants
#define BB      64      // batch
#define HL      8       // hat_L
#define NPTS    16      // N
#define DDIM    32      // d
#define FLAYER  512     // N*d
#define FTOT    4096    // hat_L*N*d
#define NCHUNK  16      // feature chunks per layer == nodes (CF == DDIM)
#define NUPPER  2080    // upper-triangle (incl diag) elements of 64x64
#define NW_SYM  17      // waiter blocks per symmetric type (17*128 >= 2080)
#define NWAIT   66      // 17 + 17 + 32
#define NBLK    202     // 128 heavy + 8 sca + 66 waiters
// blk 0..127  : gram+cov (t,nn) -> layer gate -> sfa(t,nn)
// blk 128..135: sca layer t
// blk 136..201: fused Wnum+exo, gated on gram counter
//               ids 0..16 type0(upper-tri), 17..33 type1(upper-tri), 34..65 type2(full)

// -------- device scratch (no allocations allowed) --------
__device__ float g_P[3 * HL * NCHUNK * 4096];        // chunk Gram partials (ss/tt upper-only)
__device__ float g_Ct[HL * NPTS * DDIM * DDIM];      // TARGET node covariances /63
__device__ float g_Wpart[NWAIT * 8];                 // per-waiter per-layer norm partials
__device__ float g_exo_part[NWAIT];                  // per-waiter exo norm partials
__device__ float g_sca[HL];
__device__ float g_sfa[HL * NPTS];
__device__ unsigned int g_cnt_layer[HL];             // monotonic per-layer producer counters
__device__ unsigned int g_cnt_gram;                  // monotonic gram-producer counter
__device__ unsigned int g_wcnt;                      // waiter ticket counter
__device__ unsigned int g_done;                      // completion ticket

// ---- packed fp32 helpers (sm_100+ f32x2 pipe: 2 MACs per FFMA-rate slot) ----
__device__ __forceinline__ unsigned long long pk(float lo, float hi) {
    unsigned long long v;
    asm("mov.b64 %0, {%1, %2};" : "=l"(v)
        : "r"(__float_as_uint(lo)), "r"(__float_as_uint(hi)));
    return v;
}
__device__ __forceinline__ float2 upk(unsigned long long v) {
    unsigned int lo, hi;
    asm("mov.b64 {%0, %1}, %2;" : "=r"(lo), "=r"(hi) : "l"(v));
    return make_float2(__uint_as_float(lo), __uint_as_float(hi));
}
__device__ __forceinline__ void fma2(unsigned long long& d,
                                     unsigned long long a, unsigned long long b) {
    asm("fma.rn.f32x2 %0, %1, %2, %0;" : "+l"(d) : "l"(a), "l"(b));
}

// Closed-form triangle enumerations (exact fp32 at boundaries: half-integer squares).
__device__ __forceinline__ void upper_from_idx(int idx, int& r, int& c) {     // 16x16 grid
    float rf = 16.5f - sqrtf(272.25f - 2.0f * (float)idx);
    r = (int)rf;
    c = r + idx - (16 * r - (r * (r - 1)) / 2);
}
__device__ __forceinline__ void lower_from_idx(int idx, int& r, int& c) {     // 16x16 grid
    float rf = (1.0f + sqrtf(1.0f + 8.0f * (float)idx)) * 0.5f;
    r = (int)rf;
    c = idx - (r * (r - 1)) / 2;
}
__device__ __forceinline__ void upper8_from_idx(int idx, int& r, int& c) {    // 8x8 grid
    float rf = 8.5f - sqrtf(72.25f - 2.0f * (float)idx);
    r = (int)rf;
    c = r + idx - (8 * r - (r * (r - 1)) / 2);
}
__device__ __forceinline__ void upper64_from_idx(int u, int& i, int& j) {     // 64x64 elem grid
    float rf = 64.5f - sqrtf(4160.25f - 2.0f * (float)u);
    i = (int)rf;
    j = i + u - (64 * i - (i * (i - 1)) / 2);
}

// Acquire-spin until *p >= target (monotonic counter).
__device__ __forceinline__ void spin_until(unsigned int* p, unsigned int target) {
    while (true) {
        unsigned int v;
        asm volatile("ld.acquire.gpu.u32 %0, [%1];" : "=r"(v) : "l"(p));
        if ((int)(v - target) >= 0) break;
        __nanosleep(32);
    }
}

__global__ void __launch_bounds__(256, 2) fused_all(
        const float* __restrict__ Zs, const float* __restrict__ Es,
        const float* __restrict__ Zt, const float* __restrict__ Et,
        float* __restrict__ out) {
    int blk = blockIdx.x, tid = threadIdx.x;

    __shared__ __align__(16) float St_s[DDIM][68];   // [f][b] transposed, padded
    __shared__ __align__(16) float St_t[DDIM][68];
    __shared__ __align__(16) float Csm[DDIM * DDIM]; // own SOURCE covariance /63
    __shared__ float sm_ps[DDIM * 8], sm_pt[DDIM * 8];
    __shared__ float sm_ms[DDIM], sm_mt[DDIM];
    __shared__ float red[256];
    __shared__ float sm_st[16], sm_tt[16], sm_ss;
    __shared__ float smr[4][9];
    __shared__ unsigned int sm_last;

    if (blk < 128) {
        // ============ heavy block (t, nn): gram + cov, then sfa ============
        int t = blk >> 4, nn = blk & 15;
        int fbase = t * FLAYER + nn * DDIM;
        int f0 = tid & 31, b0 = tid >> 5;
        float ps = 0.f, pt = 0.f;
        #pragma unroll
        for (int j = 0; j < 8; j++) {
            int b = b0 + 8 * j;
            float vs = Zs[b * FTOT + fbase + f0];
            float vt = Zt[b * FTOT + fbase + f0];
            St_s[f0][b] = vs; ps += vs;
            St_t[f0][b] = vt; pt += vt;
        }
        sm_ps[f0 * 8 + b0] = ps;
        sm_pt[f0 * 8 + b0] = pt;
        __syncthreads();
        if (tid < 64) {
            int f = tid & 31;
            float* P = (tid < 32) ? sm_ps : sm_pt;
            float m = 0.f;
            #pragma unroll
            for (int j = 0; j < 8; j++) m += P[f * 8 + j];
            m *= (1.0f / (float)BB);
            if (tid < 32) sm_ms[f] = m; else sm_mt[f] = m;
        }
        __syncthreads();
        {
            float ms = sm_ms[f0], mt = sm_mt[f0];
            #pragma unroll
            for (int j = 0; j < 8; j++) {
                int b = b0 + 8 * j;
                St_s[f0][b] -= ms;
                St_t[f0][b] -= mt;
            }
        }
        __syncthreads();

        float* p0 = &g_P[((0 * HL + t) * NCHUNK + nn) * 4096];
        float* p1 = &g_P[((1 * HL + t) * NCHUNK + nn) * 4096];
        float* p2 = &g_P[((2 * HL + t) * NCHUNK + nn) * 4096];
        int w = tid >> 5;

        if (w < 5) {
            // 3-type 4x4 tile via packed f32x2: 136 upper + 24 padding (lower, st-only)
            // ss/tt: upper tiles stored WITHOUT mirrors (waiters use symmetry weights)
            int r, c;
            bool is_upper = (tid < 136);
            if (is_upper) upper_from_idx(tid, r, c);
            else          lower_from_idx(tid - 136, r, c);

            unsigned long long ss2[4][2] = {}, tt2[4][2] = {}, st2[4][2] = {};
            #pragma unroll 4
            for (int f = 0; f < DDIM; f++) {
                float4 va = *(const float4*)&St_s[f][4 * r];
                float4 vb = *(const float4*)&St_s[f][4 * c];
                float4 wa = *(const float4*)&St_t[f][4 * r];
                float4 wb = *(const float4*)&St_t[f][4 * c];
                unsigned long long Bs2[2] = { pk(vb.x, vb.y), pk(vb.z, vb.w) };
                unsigned long long Bt2[2] = { pk(wb.x, wb.y), pk(wb.z, wb.w) };
                float As[4] = { va.x, va.y, va.z, va.w };
                float At[4] = { wa.x, wa.y, wa.z, wa.w };
                #pragma unroll
                for (int i = 0; i < 4; i++) {
                    unsigned long long Asb = pk(As[i], As[i]);
                    unsigned long long Atb = pk(At[i], At[i]);
                    fma2(ss2[i][0], Asb, Bs2[0]); fma2(ss2[i][1], Asb, Bs2[1]);
                    fma2(tt2[i][0], Atb, Bt2[0]); fma2(tt2[i][1], Atb, Bt2[1]);
                    fma2(st2[i][0], Asb, Bt2[0]); fma2(st2[i][1], Asb, Bt2[1]);
                }
            }
            #pragma unroll
            for (int i = 0; i < 4; i++) {
                float2 a0 = upk(st2[i][0]), a1 = upk(st2[i][1]);
                *(float4*)&p2[(4 * r + i) * 64 + 4 * c] =
                    make_float4(a0.x, a0.y, a1.x, a1.y);
            }
            if (is_upper) {
                #pragma unroll
                for (int i = 0; i < 4; i++) {
                    int o = (4 * r + i) * 64 + 4 * c;
                    float2 s0 = upk(ss2[i][0]), s1 = upk(ss2[i][1]);
                    float2 t0 = upk(tt2[i][0]), t1 = upk(tt2[i][1]);
                    *(float4*)&p0[o] = make_float4(s0.x, s0.y, s1.x, s1.y);
                    *(float4*)&p1[o] = make_float4(t0.x, t0.y, t1.x, t1.y);
                }
                // no mirror stores: consumers enumerate upper triangle only
            }
        } else {
            // st-only 4x4 tile (lower tiles 24..119, packed)
            int lid160 = tid - 160;           // 0..95
            int r, c;
            lower_from_idx(24 + lid160, r, c);
            unsigned long long st2[4][2] = {};
            #pragma unroll 4
            for (int f = 0; f < DDIM; f++) {
                float4 va = *(const float4*)&St_s[f][4 * r];
                float4 wb = *(const float4*)&St_t[f][4 * c];
                unsigned long long Bt2[2] = { pk(wb.x, wb.y), pk(wb.z, wb.w) };
                float As[4] = { va.x, va.y, va.z, va.w };
                #pragma unroll
                for (int i = 0; i < 4; i++) {
                    unsigned long long Asb = pk(As[i], As[i]);
                    fma2(st2[i][0], Asb, Bt2[0]); fma2(st2[i][1], Asb, Bt2[1]);
                }
            }
            #pragma unroll
            for (int i = 0; i < 4; i++) {
                float2 a0 = upk(st2[i][0]), a1 = upk(st2[i][1]);
                *(float4*)&p2[(4 * r + i) * 64 + 4 * c] =
                    make_float4(a0.x, a0.y, a1.x, a1.y);
            }

            // ---- node covariance: 4x4 tiles on 8x8 upper grid (36 tiles) ----
            const float inv63 = 1.0f / 63.0f;
            int cbase = (t * NPTS + nn) * (DDIM * DDIM);
            int wl = lid160 >> 5;             // 0..2
            int lane5 = lid160 & 31;
            int ctile = lane5 * 3 + wl;       // 0..35 for lane5 < 12
            if (lane5 < 12) {
                int r2, c2;
                upper8_from_idx(ctile, r2, c2);
                {   // SOURCE tensor
                    unsigned long long acc[4][4] = {};
                    #pragma unroll 2
                    for (int k = 0; k < 16; k++) {
                        ulonglong2 A[4], B[4];
                        #pragma unroll
                        for (int i = 0; i < 4; i++) {
                            A[i] = *(const ulonglong2*)&St_s[4 * r2 + i][4 * k];
                            B[i] = *(const ulonglong2*)&St_s[4 * c2 + i][4 * k];
                        }
                        #pragma unroll
                        for (int i = 0; i < 4; i++)
                            #pragma unroll
                            for (int j = 0; j < 4; j++) {
                                fma2(acc[i][j], A[i].x, B[j].x);
                                fma2(acc[i][j], A[i].y, B[j].y);
                            }
                    }
                    #pragma unroll
                    for (int i = 0; i < 4; i++)
                        #pragma unroll
                        for (int j = 0; j < 4; j++) {
                            float2 u = upk(acc[i][j]);
                            float v = (u.x + u.y) * inv63;
                            Csm[(4 * r2 + i) * DDIM + 4 * c2 + j] = v;
                            if (r2 < c2) Csm[(4 * c2 + j) * DDIM + 4 * r2 + i] = v;
                        }
                }
                {   // TARGET tensor
                    unsigned long long acc[4][4] = {};
                    #pragma unroll 2
                    for (int k = 0; k < 16; k++) {
                        ulonglong2 A[4], B[4];
                        #pragma unroll
                        for (int i = 0; i < 4; i++) {
                            A[i] = *(const ulonglong2*)&St_t[4 * r2 + i][4 * k];
                            B[i] = *(const ulonglong2*)&St_t[4 * c2 + i][4 * k];
                        }
                        #pragma unroll
                        for (int i = 0; i < 4; i++)
                            #pragma unroll
                            for (int j = 0; j < 4; j++) {
                                fma2(acc[i][j], A[i].x, B[j].x);
                                fma2(acc[i][j], A[i].y, B[j].y);
                            }
                    }
                    #pragma unroll
                    for (int i = 0; i < 4; i++)
                        #pragma unroll
                        for (int j = 0; j < 4; j++) {
                            float2 u = upk(acc[i][j]);
                            float v = (u.x + u.y) * inv63;
                            g_Ct[cbase + (4 * r2 + i) * DDIM + 4 * c2 + j] = v;
                            if (r2 < c2) g_Ct[cbase + (4 * c2 + j) * DDIM + 4 * r2 + i] = v;
                        }
                }
            }
        }

        // -------- publish + wait for layer-t producers --------
        __syncthreads();
        if (tid == 0) {
            __threadfence();
            atomicAdd(&g_cnt_gram, 1u);
            unsigned int tk = atomicAdd(&g_cnt_layer[t], 1u);
            spin_until(&g_cnt_layer[t], (tk / 16u + 1u) * 16u);
        }
        __syncthreads();

        // -------- sfa(t, nn): Cs from smem, Ct from gmem --------
        {
            int n = nn;
            int lane = tid & 31;
            const float* Ct1 = &g_Ct[(t * NPTS + w)     * (DDIM * DDIM)];
            const float* Ct2 = &g_Ct[(t * NPTS + w + 8) * (DDIM * DDIM)];
            float sqs = 0.f, d1 = 0.f, q1 = 0.f, d2 = 0.f, q2 = 0.f;
            #pragma unroll
            for (int kk = 0; kk < 8; kk++) {
                int idx = kk * 128 + lane * 4;
                float4 a  = *(const float4*)&Csm[idx];
                float4 b1 = *(const float4*)&Ct1[idx];
                float4 b2 = *(const float4*)&Ct2[idx];
                sqs += a.x*a.x + a.y*a.y + a.z*a.z + a.w*a.w;
                d1  += a.x*b1.x + a.y*b1.y + a.z*b1.z + a.w*b1.w;
                q1  += b1.x*b1.x + b1.y*b1.y + b1.z*b1.z + b1.w*b1.w;
                d2  += a.x*b2.x + a.y*b2.y + a.z*b2.z + a.w*b2.w;
                q2  += b2.x*b2.x + b2.y*b2.y + b2.z*b2.z + b2.w*b2.w;
            }
            #pragma unroll
            for (int o = 16; o > 0; o >>= 1) {
                sqs += __shfl_xor_sync(0xFFFFFFFFu, sqs, o);
                d1  += __shfl_xor_sync(0xFFFFFFFFu, d1, o);
                q1  += __shfl_xor_sync(0xFFFFFFFFu, q1, o);
                d2  += __shfl_xor_sync(0xFFFFFFFFu, d2, o);
                q2  += __shfl_xor_sync(0xFFFFFFFFu, q2, o);
            }
            if (lane == 0) {
                sm_st[w] = d1;  sm_st[w + 8] = d2;
                sm_tt[w] = q1;  sm_tt[w + 8] = q2;
                if (w == 0) sm_ss = sqs;
            }
            __syncthreads();
            if (tid == 0) {
                float ss = sm_ss;
                float Dsum = 0.f, pos = 0.f;
                #pragma unroll
                for (int j = 0; j < 16; j++) {
                    float Dj = (ss + sm_tt[j] - 2.0f * sm_st[j]) * (1.0f / 4096.0f);
                    Dsum += Dj;
                    if (j == n) pos = Dj;
                }
                float neg = Dsum - pos;
                float ep = expf(pos);
                g_sfa[t * NPTS + n] = logf(ep + neg + 1e-8f) - pos;
            }
        }
    } else if (blk < 136) {
        // ============ L_sca for layer t ============
        int t = blk - 128;
        int base = t * (NPTS * NPTS) + tid;
        float ss = 0.f, sqs = 0.f, st = 0.f, sqt = 0.f;
        #pragma unroll 16
        for (int b = 0; b < BB; b++) {
            float a = Es[b * (HL * NPTS * NPTS) + base];
            ss += a; sqs += a * a;
            float ccc = Et[b * (HL * NPTS * NPTS) + base];
            st += ccc; sqt += ccc * ccc;
        }
        float var_s = (sqs - ss * ss * (1.0f / (float)BB)) * (1.0f / (float)(BB - 1));
        float var_t = (sqt - st * st * (1.0f / (float)BB)) * (1.0f / (float)(BB - 1));
        float d = var_s - var_t;
        red[tid] = d * d * 0.25f;
        __syncthreads();
        for (int s2 = 128; s2 > 0; s2 >>= 1) {
            if (tid < s2) red[tid] += red[tid + s2];
            __syncthreads();
        }
        if (tid == 0) g_sca[t] = red[0] * (1.0f / 256.0f);
    } else {
        // ============ fused Wnum + exo, gated on gram counter ============
        if (tid == 0) {
            unsigned int tk = atomicAdd(&g_wcnt, 1u);
            spin_until(&g_cnt_gram, (tk / (unsigned)NWAIT + 1u) * 128u);
        }
        __syncthreads();

        int id = blk - 136;                   // 0..65
        float wv[9];
        bool active = false;
        int type, elem = 0;
        float wgt = 1.f;
        if (id < NW_SYM) {                    // type 0 upper triangle
            type = 0;
            int u = id * 128 + tid;
            if (tid < 128 && u < NUPPER) {
                int i2, j2; upper64_from_idx(u, i2, j2);
                elem = i2 * 64 + j2;
                wgt = (i2 == j2) ? 1.0f : 2.0f;
                active = true;
            }
        } else if (id < 2 * NW_SYM) {         // type 1 upper triangle
            type = 1;
            int u = (id - NW_SYM) * 128 + tid;
            if (tid < 128 && u < NUPPER) {
                int i2, j2; upper64_from_idx(u, i2, j2);
                elem = i2 * 64 + j2;
                wgt = (i2 == j2) ? 1.0f : 2.0f;
                active = true;
            }
        } else {                              // type 2 full (st not symmetric)
            type = 2;
            int seg = id - 2 * NW_SYM;        // 0..31
            if (tid < 128) {
                elem = seg * 128 + tid;
                active = true;
            }
        }
        if (active) {
            const float* Pbase = &g_P[type * HL * NCHUNK * 4096];
            float e = 0.f;
            #pragma unroll
            for (int t = 0; t < HL; t++) {
                float v = 0.f;
                #pragma unroll
                for (int c = 0; c < NCHUNK; c++)
                    v += Pbase[(t * NCHUNK + c) * 4096 + elem];
                wv[t] = wgt * v * v;
                e += v;
            }
            wv[8] = wgt * e * e;
        } else {
            #pragma unroll
            for (int k = 0; k < 9; k++) wv[k] = 0.f;
        }
        int w = tid >> 5, lane = tid & 31;
        if (w < 4) {
            #pragma unroll
            for (int k = 0; k < 9; k++) {
                float s = wv[k];
                #pragma unroll
                for (int o = 16; o > 0; o >>= 1)
                    s += __shfl_xor_sync(0xFFFFFFFFu, s, o);
                if (lane == 0) smr[w][k] = s;
            }
        }
        __syncthreads();
        if (tid < 9) {
            float s = 0.f;
            #pragma unroll
            for (int ww = 0; ww < 4; ww++) s += smr[ww][tid];
            if (tid < 8) g_Wpart[id * 8 + tid] = s;
            else         g_exo_part[id] = s;
        }
    }

    // ================= finisher: last done-ticket combines =================
    __syncthreads();
    if (tid == 0) {
        __threadfence();
        unsigned int ticket = atomicAdd(&g_done, 1u);
        sm_last = ((ticket % NBLK) == (NBLK - 1)) ? 1u : 0u;
    }
    __syncthreads();
    if (sm_last && tid < 32) {
        __threadfence();
        int lane = tid;
        const float exo_scale = (float)(1.0 / (3969.0 * 4.0 * 16777216.0));
        const float w_scale   = (float)(1.0 / (3969.0 * 4.0 * 262144.0));
        float val = 0.f;
        if (lane < 8) {
            int t = lane;
            float w0 = 0.f, w1 = 0.f, w2 = 0.f;
            #pragma unroll
            for (int id = 0; id < NW_SYM; id++)           w0 += g_Wpart[id * 8 + t];
            #pragma unroll
            for (int id = NW_SYM; id < 2 * NW_SYM; id++)  w1 += g_Wpart[id * 8 + t];
            #pragma unroll 8
            for (int id = 2 * NW_SYM; id < NWAIT; id++)   w2 += g_Wpart[id * 8 + t];
            float W = (w0 + w1 - 2.0f * w2) * w_scale;
            float sfa = 0.f;
            #pragma unroll
            for (int n = 0; n < NPTS; n++) sfa += g_sfa[t * NPTS + n];
            sfa *= (1.0f / (float)NPTS);
            val = W * (0.1f * g_sca[t] + 0.1f * sfa) * (1.0f / (float)HL);
        } else {
            // lanes 8..31: 24 lanes x 3 entries cover 66 exo partials (guarded)
            #pragma unroll
            for (int k = 0; k < 3; k++) {
                int idx = (lane - 8) + 24 * k;            // 0..71
                if (idx < NWAIT) {
                    float coef = (idx >= 2 * NW_SYM) ? -2.0f : 1.0f;
                    val += g_exo_part[idx] * coef * exo_scale;
                }
            }
        }
        #pragma unroll
        for (int o = 16; o > 0; o >>= 1)
            val += __shfl_xor_sync(0xFFFFFFFFu, val, o);
        if (lane == 0) out[0] = val;
    }
}

// ============================================================
extern "C" void kernel_launch(void* const* d_in, const int* in_sizes, int n_in,
                              void* d_out, int out_size) {
    const float* Zs = (const float*)d_in[0];
    const float* Es = (const float*)d_in[1];
    const float* Zt = (const float*)d_in[2];
    const float* Et = (const float*)d_in[3];
    float* out = (float*)d_out;

    fused_all<<<NBLK, 256>>>(Zs, Es, Zt, Et, out);
}

// round 17
// speedup vs baseline: 1.0619x; 1.0619x over previous
#include <cuda_runtime.h>

// Problem constants
#define BB      64      // batch
#define HL      8       // hat_L
#define NPTS    16      // N
#define DDIM    32      // d
#define FLAYER  512     // N*d
#define FTOT    4096    // hat_L*N*d
#define NCHUNK  16      // feature chunks per layer == nodes (CF == DDIM)
#define NBLK    232     // 128 heavy + 8 sca + 96 waiters
// blk 0..127  : gram+cov (t,nn) -> layer gate -> sfa(t,nn)
// blk 128..135: sca layer t
// blk 136..231: fused Wnum+exo (type, seg32), gated on gram counter

// -------- device scratch (no allocations allowed) --------
__device__ float g_P[3 * HL * NCHUNK * 4096];        // chunk Gram partials : 6 MB
__device__ float g_Ct[HL * NPTS * DDIM * DDIM];      // TARGET node covariances /63
__device__ float g_Wpart[96 * 8];                    // per-(type,seg) per-layer norm partials
__device__ float g_exo_part[96];                     // per-(type,seg) exo norm partials
__device__ float g_sca[HL];
__device__ float g_sfa[HL * NPTS];
__device__ unsigned int g_cnt_layer[HL];             // monotonic per-layer producer counters
__device__ unsigned int g_cnt_gram;                  // monotonic gram-producer counter
__device__ unsigned int g_wcnt;                      // waiter ticket counter
__device__ unsigned int g_done;                      // completion ticket

// ---- packed fp32 helpers (sm_100+ f32x2 pipe: 2 MACs per FFMA-rate slot) ----
__device__ __forceinline__ unsigned long long pk(float lo, float hi) {
    unsigned long long v;
    asm("mov.b64 %0, {%1, %2};" : "=l"(v)
        : "r"(__float_as_uint(lo)), "r"(__float_as_uint(hi)));
    return v;
}
__device__ __forceinline__ float2 upk(unsigned long long v) {
    unsigned int lo, hi;
    asm("mov.b64 {%0, %1}, %2;" : "=r"(lo), "=r"(hi) : "l"(v));
    return make_float2(__uint_as_float(lo), __uint_as_float(hi));
}
__device__ __forceinline__ void fma2(unsigned long long& d,
                                     unsigned long long a, unsigned long long b) {
    asm("fma.rn.f32x2 %0, %1, %2, %0;" : "+l"(d) : "l"(a), "l"(b));
}

// Closed-form triangle enumerations (exact fp32 at boundaries).
__device__ __forceinline__ void upper_from_idx(int idx, int& r, int& c) {     // 16x16 grid
    float rf = 16.5f - sqrtf(272.25f - 2.0f * (float)idx);
    r = (int)rf;
    c = r + idx - (16 * r - (r * (r - 1)) / 2);
}
__device__ __forceinline__ void lower_from_idx(int idx, int& r, int& c) {     // 16x16 grid
    float rf = (1.0f + sqrtf(1.0f + 8.0f * (float)idx)) * 0.5f;
    r = (int)rf;
    c = idx - (r * (r - 1)) / 2;
}
__device__ __forceinline__ void upper8_from_idx(int idx, int& r, int& c) {    // 8x8 grid
    float rf = 8.5f - sqrtf(72.25f - 2.0f * (float)idx);
    r = (int)rf;
    c = r + idx - (8 * r - (r * (r - 1)) / 2);
}

// Acquire-spin until *p >= target (monotonic counter).
__device__ __forceinline__ void spin_until(unsigned int* p, unsigned int target) {
    while (true) {
        unsigned int v;
        asm volatile("ld.acquire.gpu.u32 %0, [%1];" : "=r"(v) : "l"(p));
        if ((int)(v - target) >= 0) break;
        __nanosleep(32);
    }
}

__global__ void __launch_bounds__(256, 2) fused_all(
        const float* __restrict__ Zs, const float* __restrict__ Es,
        const float* __restrict__ Zt, const float* __restrict__ Et,
        float* __restrict__ out) {
    int blk = blockIdx.x, tid = threadIdx.x;

    __shared__ __align__(16) float St_s[DDIM][68];   // [f][b] transposed, padded (row = 272B, 16B-aligned)
    __shared__ __align__(16) float St_t[DDIM][68];
    __shared__ __align__(16) float Csm[DDIM * DDIM]; // own SOURCE covariance /63
    __shared__ float sm_ps[DDIM * 8], sm_pt[DDIM * 8];
    __shared__ float sm_ms[DDIM], sm_mt[DDIM];
    __shared__ float red[256];
    __shared__ float sm_st[16], sm_tt[16], sm_ss;
    __shared__ float smr[4][9];
    __shared__ unsigned int sm_last;

    if (blk < 128) {
        // ============ heavy block (t, nn): gram + cov, then sfa ============
        int t = blk >> 4, nn = blk & 15;
        int fbase = t * FLAYER + nn * DDIM;
        int f0 = tid & 31, b0 = tid >> 5;
        float ps = 0.f, pt = 0.f;
        #pragma unroll
        for (int j = 0; j < 8; j++) {
            int b = b0 + 8 * j;
            float vs = Zs[b * FTOT + fbase + f0];
            float vt = Zt[b * FTOT + fbase + f0];
            St_s[f0][b] = vs; ps += vs;
            St_t[f0][b] = vt; pt += vt;
        }
        sm_ps[f0 * 8 + b0] = ps;
        sm_pt[f0 * 8 + b0] = pt;
        __syncthreads();
        if (tid < 64) {
            int f = tid & 31;
            float* P = (tid < 32) ? sm_ps : sm_pt;
            float m = 0.f;
            #pragma unroll
            for (int j = 0; j < 8; j++) m += P[f * 8 + j];
            m *= (1.0f / (float)BB);
            if (tid < 32) sm_ms[f] = m; else sm_mt[f] = m;
        }
        __syncthreads();
        {
            float ms = sm_ms[f0], mt = sm_mt[f0];
            #pragma unroll
            for (int j = 0; j < 8; j++) {
                int b = b0 + 8 * j;
                St_s[f0][b] -= ms;
                St_t[f0][b] -= mt;
            }
        }
        __syncthreads();

        float* p0 = &g_P[((0 * HL + t) * NCHUNK + nn) * 4096];
        float* p1 = &g_P[((1 * HL + t) * NCHUNK + nn) * 4096];
        float* p2 = &g_P[((2 * HL + t) * NCHUNK + nn) * 4096];
        int w = tid >> 5;

        if (w < 5) {
            // 3-type 4x4 tile via packed f32x2: 136 upper + 24 padding (lower, st-only)
            int r, c;
            bool is_upper = (tid < 136);
            if (is_upper) upper_from_idx(tid, r, c);
            else          lower_from_idx(tid - 136, r, c);

            unsigned long long ss2[4][2] = {}, tt2[4][2] = {}, st2[4][2] = {};
            #pragma unroll 4
            for (int f = 0; f < DDIM; f++) {
                float4 va = *(const float4*)&St_s[f][4 * r];
                float4 vb = *(const float4*)&St_s[f][4 * c];
                float4 wa = *(const float4*)&St_t[f][4 * r];
                float4 wb = *(const float4*)&St_t[f][4 * c];
                unsigned long long Bs2[2] = { pk(vb.x, vb.y), pk(vb.z, vb.w) };
                unsigned long long Bt2[2] = { pk(wb.x, wb.y), pk(wb.z, wb.w) };
                float As[4] = { va.x, va.y, va.z, va.w };
                float At[4] = { wa.x, wa.y, wa.z, wa.w };
                #pragma unroll
                for (int i = 0; i < 4; i++) {
                    unsigned long long Asb = pk(As[i], As[i]);
                    unsigned long long Atb = pk(At[i], At[i]);
                    fma2(ss2[i][0], Asb, Bs2[0]); fma2(ss2[i][1], Asb, Bs2[1]);
                    fma2(tt2[i][0], Atb, Bt2[0]); fma2(tt2[i][1], Atb, Bt2[1]);
                    fma2(st2[i][0], Asb, Bt2[0]); fma2(st2[i][1], Asb, Bt2[1]);
                }
            }
            #pragma unroll
            for (int i = 0; i < 4; i++) {
                float2 a0 = upk(st2[i][0]), a1 = upk(st2[i][1]);
                *(float4*)&p2[(4 * r + i) * 64 + 4 * c] =
                    make_float4(a0.x, a0.y, a1.x, a1.y);
            }
            if (is_upper) {
                #pragma unroll
                for (int i = 0; i < 4; i++) {
                    int o = (4 * r + i) * 64 + 4 * c;
                    float2 s0 = upk(ss2[i][0]), s1 = upk(ss2[i][1]);
                    float2 t0 = upk(tt2[i][0]), t1 = upk(tt2[i][1]);
                    *(float4*)&p0[o] = make_float4(s0.x, s0.y, s1.x, s1.y);
                    *(float4*)&p1[o] = make_float4(t0.x, t0.y, t1.x, t1.y);
                }
                if (r < c) {                   // mirror (bitwise-equal values)
                    #pragma unroll
                    for (int j = 0; j < 2; j++) {
                        float2 sA[4], tA[4];
                        #pragma unroll
                        for (int i = 0; i < 4; i++) { sA[i] = upk(ss2[i][j]); tA[i] = upk(tt2[i][j]); }
                        int o0 = (4 * c + 2 * j) * 64 + 4 * r;
                        int o1 = (4 * c + 2 * j + 1) * 64 + 4 * r;
                        *(float4*)&p0[o0] = make_float4(sA[0].x, sA[1].x, sA[2].x, sA[3].x);
                        *(float4*)&p0[o1] = make_float4(sA[0].y, sA[1].y, sA[2].y, sA[3].y);
                        *(float4*)&p1[o0] = make_float4(tA[0].x, tA[1].x, tA[2].x, tA[3].x);
                        *(float4*)&p1[o1] = make_float4(tA[0].y, tA[1].y, tA[2].y, tA[3].y);
                    }
                }
            }
        } else {
            // st-only 4x4 tile (lower tiles 24..119, packed)
            int lid160 = tid - 160;           // 0..95
            int r, c;
            lower_from_idx(24 + lid160, r, c);
            unsigned long long st2[4][2] = {};
            #pragma unroll 4
            for (int f = 0; f < DDIM; f++) {
                float4 va = *(const float4*)&St_s[f][4 * r];
                float4 wb = *(const float4*)&St_t[f][4 * c];
                unsigned long long Bt2[2] = { pk(wb.x, wb.y), pk(wb.z, wb.w) };
                float As[4] = { va.x, va.y, va.z, va.w };
                #pragma unroll
                for (int i = 0; i < 4; i++) {
                    unsigned long long Asb = pk(As[i], As[i]);
                    fma2(st2[i][0], Asb, Bt2[0]); fma2(st2[i][1], Asb, Bt2[1]);
                }
            }
            #pragma unroll
            for (int i = 0; i < 4; i++) {
                float2 a0 = upk(st2[i][0]), a1 = upk(st2[i][1]);
                *(float4*)&p2[(4 * r + i) * 64 + 4 * c] =
                    make_float4(a0.x, a0.y, a1.x, a1.y);
            }

            // ---- node covariance: 4x4 tiles on 8x8 upper grid (36 tiles) ----
            // tile -> warp 5+(tile%3), lane tile/3; lanes 0..11 active per warp.
            const float inv63 = 1.0f / 63.0f;
            int cbase = (t * NPTS + nn) * (DDIM * DDIM);
            int wl = lid160 >> 5;             // 0..2
            int lane5 = lid160 & 31;
            int ctile = lane5 * 3 + wl;       // 0..35 for lane5 < 12
            if (lane5 < 12) {
                int r2, c2;
                upper8_from_idx(ctile, r2, c2);
                // SOURCE tensor
                {
                    unsigned long long acc[4][4] = {};
                    #pragma unroll 2
                    for (int k = 0; k < 16; k++) {
                        ulonglong2 A[4], B[4];
                        #pragma unroll
                        for (int i = 0; i < 4; i++) {
                            A[i] = *(const ulonglong2*)&St_s[4 * r2 + i][4 * k];
                            B[i] = *(const ulonglong2*)&St_s[4 * c2 + i][4 * k];
                        }
                        #pragma unroll
                        for (int i = 0; i < 4; i++)
                            #pragma unroll
                            for (int j = 0; j < 4; j++) {
                                fma2(acc[i][j], A[i].x, B[j].x);
                                fma2(acc[i][j], A[i].y, B[j].y);
                            }
                    }
                    #pragma unroll
                    for (int i = 0; i < 4; i++)
                        #pragma unroll
                        for (int j = 0; j < 4; j++) {
                            float2 u = upk(acc[i][j]);
                            float v = (u.x + u.y) * inv63;
                            Csm[(4 * r2 + i) * DDIM + 4 * c2 + j] = v;
                            if (r2 < c2) Csm[(4 * c2 + j) * DDIM + 4 * r2 + i] = v;
                        }
                }
                // TARGET tensor
                {
                    unsigned long long acc[4][4] = {};
                    #pragma unroll 2
                    for (int k = 0; k < 16; k++) {
                        ulonglong2 A[4], B[4];
                        #pragma unroll
                        for (int i = 0; i < 4; i++) {
                            A[i] = *(const ulonglong2*)&St_t[4 * r2 + i][4 * k];
                            B[i] = *(const ulonglong2*)&St_t[4 * c2 + i][4 * k];
                        }
                        #pragma unroll
                        for (int i = 0; i < 4; i++)
                            #pragma unroll
                            for (int j = 0; j < 4; j++) {
                                fma2(acc[i][j], A[i].x, B[j].x);
                                fma2(acc[i][j], A[i].y, B[j].y);
                            }
                    }
                    #pragma unroll
                    for (int i = 0; i < 4; i++)
                        #pragma unroll
                        for (int j = 0; j < 4; j++) {
                            float2 u = upk(acc[i][j]);
                            float v = (u.x + u.y) * inv63;
                            g_Ct[cbase + (4 * r2 + i) * DDIM + 4 * c2 + j] = v;
                            if (r2 < c2) g_Ct[cbase + (4 * c2 + j) * DDIM + 4 * r2 + i] = v;
                        }
                }
            }
        }

        // -------- publish + wait for layer-t producers --------
        __syncthreads();
        if (tid == 0) {
            __threadfence();
            atomicAdd(&g_cnt_gram, 1u);
            unsigned int tk = atomicAdd(&g_cnt_layer[t], 1u);
            spin_until(&g_cnt_layer[t], (tk / 16u + 1u) * 16u);
        }
        __syncthreads();

        // -------- sfa(t, nn): Cs from smem, Ct from gmem --------
        {
            int n = nn;
            int lane = tid & 31;
            const float* Ct1 = &g_Ct[(t * NPTS + w)     * (DDIM * DDIM)];
            const float* Ct2 = &g_Ct[(t * NPTS + w + 8) * (DDIM * DDIM)];
            float sqs = 0.f, d1 = 0.f, q1 = 0.f, d2 = 0.f, q2 = 0.f;
            #pragma unroll
            for (int kk = 0; kk < 8; kk++) {
                int idx = kk * 128 + lane * 4;
                float4 a  = *(const float4*)&Csm[idx];
                float4 b1 = *(const float4*)&Ct1[idx];
                float4 b2 = *(const float4*)&Ct2[idx];
                sqs += a.x*a.x + a.y*a.y + a.z*a.z + a.w*a.w;
                d1  += a.x*b1.x + a.y*b1.y + a.z*b1.z + a.w*b1.w;
                q1  += b1.x*b1.x + b1.y*b1.y + b1.z*b1.z + b1.w*b1.w;
                d2  += a.x*b2.x + a.y*b2.y + a.z*b2.z + a.w*b2.w;
                q2  += b2.x*b2.x + b2.y*b2.y + b2.z*b2.z + b2.w*b2.w;
            }
            #pragma unroll
            for (int o = 16; o > 0; o >>= 1) {
                sqs += __shfl_xor_sync(0xFFFFFFFFu, sqs, o);
                d1  += __shfl_xor_sync(0xFFFFFFFFu, d1, o);
                q1  += __shfl_xor_sync(0xFFFFFFFFu, q1, o);
                d2  += __shfl_xor_sync(0xFFFFFFFFu, d2, o);
                q2  += __shfl_xor_sync(0xFFFFFFFFu, q2, o);
            }
            if (lane == 0) {
                sm_st[w] = d1;  sm_st[w + 8] = d2;
                sm_tt[w] = q1;  sm_tt[w + 8] = q2;
                if (w == 0) sm_ss = sqs;
            }
            __syncthreads();
            if (tid == 0) {
                float ss = sm_ss;
                float Dsum = 0.f, pos = 0.f;
                #pragma unroll
                for (int j = 0; j < 16; j++) {
                    float Dj = (ss + sm_tt[j] - 2.0f * sm_st[j]) * (1.0f / 4096.0f);
                    Dsum += Dj;
                    if (j == n) pos = Dj;
                }
                float neg = Dsum - pos;
                float ep = expf(pos);
                g_sfa[t * NPTS + n] = logf(ep + neg + 1e-8f) - pos;
            }
        }
    } else if (blk < 136) {
        // ============ L_sca for layer t ============
        int t = blk - 128;
        int base = t * (NPTS * NPTS) + tid;
        float ss = 0.f, sqs = 0.f, st = 0.f, sqt = 0.f;
        #pragma unroll 16
        for (int b = 0; b < BB; b++) {
            float a = Es[b * (HL * NPTS * NPTS) + base];
            ss += a; sqs += a * a;
            float ccc = Et[b * (HL * NPTS * NPTS) + base];
            st += ccc; sqt += ccc * ccc;
        }
        float var_s = (sqs - ss * ss * (1.0f / (float)BB)) * (1.0f / (float)(BB - 1));
        float var_t = (sqt - st * st * (1.0f / (float)BB)) * (1.0f / (float)(BB - 1));
        float d = var_s - var_t;
        red[tid] = d * d * 0.25f;
        __syncthreads();
        for (int s2 = 128; s2 > 0; s2 >>= 1) {
            if (tid < s2) red[tid] += red[tid + s2];
            __syncthreads();
        }
        if (tid == 0) g_sca[t] = red[0] * (1.0f / 256.0f);
    } else {
        // ============ fused Wnum + exo (type, seg32): 128 elements/block ============
        if (tid == 0) {
            unsigned int tk = atomicAdd(&g_wcnt, 1u);
            spin_until(&g_cnt_gram, (tk / 96u + 1u) * 128u);
        }
        __syncthreads();

        int id = blk - 136;                   // 0..95
        int type = id / 32, seg = id % 32;
        float wv[9];
        if (tid < 128) {
            const float* Pbase = &g_P[type * HL * NCHUNK * 4096];
            int i = seg * 128 + tid;          // one element per thread (coalesced)
            float e = 0.f;
            #pragma unroll
            for (int t = 0; t < HL; t++) {
                float v = 0.f;
                #pragma unroll
                for (int c = 0; c < NCHUNK; c++)
                    v += Pbase[(t * NCHUNK + c) * 4096 + i];
                wv[t] = v * v;
                e += v;
            }
            wv[8] = e * e;
        } else {
            #pragma unroll
            for (int k = 0; k < 9; k++) wv[k] = 0.f;
        }
        int w = tid >> 5, lane = tid & 31;
        if (w < 4) {
            #pragma unroll
            for (int k = 0; k < 9; k++) {
                float s = wv[k];
                #pragma unroll
                for (int o = 16; o > 0; o >>= 1)
                    s += __shfl_xor_sync(0xFFFFFFFFu, s, o);
                if (lane == 0) smr[w][k] = s;
            }
        }
        __syncthreads();
        if (tid < 9) {
            float s = 0.f;
            #pragma unroll
            for (int ww = 0; ww < 4; ww++) s += smr[ww][tid];
            if (tid < 8) g_Wpart[id * 8 + tid] = s;
            else         g_exo_part[id] = s;
        }
    }

    // ================= finisher: last done-ticket combines =================
    __syncthreads();
    if (tid == 0) {
        __threadfence();
        unsigned int ticket = atomicAdd(&g_done, 1u);
        sm_last = ((ticket % NBLK) == (NBLK - 1)) ? 1u : 0u;
    }
    __syncthreads();
    if (sm_last && tid < 32) {
        __threadfence();
        int lane = tid;
        const float exo_scale = (float)(1.0 / (3969.0 * 4.0 * 16777216.0));
        const float w_scale   = (float)(1.0 / (3969.0 * 4.0 * 262144.0));
        float val = 0.f;
        if (lane < 8) {
            int t = lane;
            float w0 = 0.f, w1 = 0.f, w2 = 0.f;
            #pragma unroll 8
            for (int seg = 0; seg < 32; seg++) {
                w0 += g_Wpart[(0 * 32 + seg) * 8 + t];
                w1 += g_Wpart[(1 * 32 + seg) * 8 + t];
                w2 += g_Wpart[(2 * 32 + seg) * 8 + t];
            }
            float W = (w0 + w1 - 2.0f * w2) * w_scale;
            float sfa = 0.f;
            #pragma unroll
            for (int n = 0; n < NPTS; n++) sfa += g_sfa[t * NPTS + n];
            sfa *= (1.0f / (float)NPTS);
            val = W * (0.1f * g_sca[t] + 0.1f * sfa) * (1.0f / (float)HL);
        } else {
            // lanes 8..31: 24 lanes x 4 entries = 96 exo partials
            #pragma unroll
            for (int k = 0; k < 4; k++) {
                int idx = (lane - 8) * 4 + k;     // 0..95
                int type = idx / 32;
                float coef = (type == 2) ? -2.0f : 1.0f;
                val += g_exo_part[idx] * coef * exo_scale;
            }
        }
        #pragma unroll
        for (int o = 16; o > 0; o >>= 1)
            val += __shfl_xor_sync(0xFFFFFFFFu, val, o);
        if (lane == 0) out[0] = val;
    }
}

// ============================================================
extern "C" void kernel_launch(void* const* d_in, const int* in_sizes, int n_in,
                              void* d_out, int out_size) {
    const float* Zs = (const float*)d_in[0];
    const float* Es = (const float*)d_in[1];
    const float* Zt = (const float*)d_in[2];
    const float* Et = (const float*)d_in[3];
    float* out = (float*)d_out;

    fused_all<<<NBLK, 256>>>(Zs, Es, Zt, Et, out);
}